// round 1
// baseline (speedup 1.0000x reference)
#include <cuda_runtime.h>

#define NFFT     1024
#define PLANE    1092            // 1024 + swizzle headroom; PLANE % 32 == 4
#define ROWS     8               // packed complex rows per CTA (= 16 real rows)
#define NTHREADS 512
#define PI_F     3.14159265358979323846f

__device__ __forceinline__ int swz(int p) { return p + (p >> 4); }

// One radix-2 stage on 16 register-resident complex elements.
// Elements are at positions p = base + D*j.  Actual stride S = D*H.
// Forward (DIF):  out0 = x0+x1 ; out1 = (x0-x1)*e^{-i*pi*jt/S}
// Inverse (DIT):  t = e^{+i*pi*jt/S}*x1 ; out0 = x0+t ; out1 = x0-t
template<int H, int D, bool INV>
__device__ __forceinline__ void bf_stage(float* xr, float* xi, int base) {
    const int S = D * H;
    const float coef = (INV ? PI_F : -PI_F) / (float)S;
    #pragma unroll
    for (int j = 0; j < 16; ++j) {
        if ((j & H) == 0) {
            const int j2 = j + H;
            int jt = (base + D * (j & (H - 1))) & (S - 1);
            float ang = coef * (float)jt;
            float sn, cs;
            __sincosf(ang, &sn, &cs);
            if (!INV) {
                float tr = xr[j] - xr[j2];
                float ti = xi[j] - xi[j2];
                xr[j] += xr[j2];
                xi[j] += xi[j2];
                xr[j2] = tr * cs - ti * sn;
                xi[j2] = tr * sn + ti * cs;
            } else {
                float tr = xr[j2] * cs - xi[j2] * sn;
                float ti = xr[j2] * sn + xi[j2] * cs;
                xr[j2] = xr[j] - tr;
                xi[j2] = xi[j] - ti;
                xr[j]  += tr;
                xi[j]  += ti;
            }
        }
    }
}

// One CTA: 8 packed complex rows (real rows bi and bi+4096, bi = bc*512 + a0+row).
// 64 threads per row, 16 complex elements per thread.
// Forward groups: A(512,256,128,64) B(32,16,8,4) C(2,1); filter; inverse C(1,2,4,8) B2(16,32,64,128) A(256,512)
__global__ void __launch_bounds__(NTHREADS, 2)
fbp_kernel(const float* __restrict__ x, const float* __restrict__ filt,
           float* __restrict__ out)
{
    extern __shared__ float smem[];
    float* sre = smem;
    float* sim = smem + ROWS * PLANE;

    const int tid = threadIdx.x;
    const int bc  = blockIdx.x >> 6;         // 0..7
    const int a0  = (blockIdx.x & 63) << 3;  // 0..504 step 8

    const float* __restrict__ xre = x + bc * 262144 + a0;        // real-part rows
    const float* __restrict__ xim = x + (bc + 8) * 262144 + a0;  // imag-part rows

    // ---- global -> smem (coalesced 32B sectors), zero-pad upper half ----
    #pragma unroll
    for (int k = 0; k < 8; ++k) {
        int idx  = tid + NTHREADS * k;   // 0..4095
        int row  = idx & 7;
        int s    = idx >> 3;             // 0..511
        float vr = __ldg(xre + s * 512 + row);
        float vi = __ldg(xim + s * 512 + row);
        int qb = row * PLANE;
        sre[qb + swz(s)] = vr;
        sim[qb + swz(s)] = vi;
        sre[qb + swz(s + 512)] = 0.0f;
        sim[qb + swz(s + 512)] = 0.0f;
    }
    __syncthreads();

    const int row = tid >> 6;    // 0..7
    const int r   = tid & 63;    // 0..63
    float* __restrict__ pre = sre + row * PLANE;
    float* __restrict__ pim = sim + row * PLANE;

    float xr[16], xi[16];

    // ---- forward group A: layout p = r + 64j ----
    #pragma unroll
    for (int j = 0; j < 16; ++j) {
        int q = swz(r + (j << 6));
        xr[j] = pre[q]; xi[j] = pim[q];
    }
    bf_stage<8, 64, false>(xr, xi, r);
    bf_stage<4, 64, false>(xr, xi, r);
    bf_stage<2, 64, false>(xr, xi, r);
    bf_stage<1, 64, false>(xr, xi, r);
    #pragma unroll
    for (int j = 0; j < 16; ++j) {
        int q = swz(r + (j << 6));
        pre[q] = xr[j]; pim[q] = xi[j];
    }
    __syncthreads();

    // ---- forward group B: layout p = (r>>2)*64 + (r&3) + 4j ----
    const int baseB = ((r >> 2) << 6) + (r & 3);
    #pragma unroll
    for (int j = 0; j < 16; ++j) {
        int q = swz(baseB + (j << 2));
        xr[j] = pre[q]; xi[j] = pim[q];
    }
    bf_stage<8, 4, false>(xr, xi, baseB);
    bf_stage<4, 4, false>(xr, xi, baseB);
    bf_stage<2, 4, false>(xr, xi, baseB);
    bf_stage<1, 4, false>(xr, xi, baseB);
    #pragma unroll
    for (int j = 0; j < 16; ++j) {
        int q = swz(baseB + (j << 2));
        pre[q] = xr[j]; pim[q] = xi[j];
    }
    __syncthreads();

    // ---- forward group C + filter + inverse group C (no exchange at junction) ----
    const int baseC = r << 4;    // layout p = 16r + j (contiguous)
    #pragma unroll
    for (int j = 0; j < 16; ++j) {
        int q = swz(baseC + j);
        xr[j] = pre[q]; xi[j] = pim[q];
    }
    bf_stage<2, 1, false>(xr, xi, baseC);
    bf_stage<1, 1, false>(xr, xi, baseC);
    #pragma unroll
    for (int j = 0; j < 16; ++j) {   // filter in bit-reversed domain; fold 1/n scale
        float f = __ldg(filt + baseC + j) * (1.0f / 1024.0f);
        xr[j] *= f; xi[j] *= f;
    }
    bf_stage<1, 1, true>(xr, xi, baseC);
    bf_stage<2, 1, true>(xr, xi, baseC);
    bf_stage<4, 1, true>(xr, xi, baseC);
    bf_stage<8, 1, true>(xr, xi, baseC);
    #pragma unroll
    for (int j = 0; j < 16; ++j) {
        int q = swz(baseC + j);
        pre[q] = xr[j]; pim[q] = xi[j];
    }
    __syncthreads();

    // ---- inverse group B2: layout p = (r>>4)*256 + (r&15) + 16j ----
    const int baseB2 = ((r >> 4) << 8) + (r & 15);
    #pragma unroll
    for (int j = 0; j < 16; ++j) {
        int q = swz(baseB2 + (j << 4));
        xr[j] = pre[q]; xi[j] = pim[q];
    }
    bf_stage<1, 16, true>(xr, xi, baseB2);
    bf_stage<2, 16, true>(xr, xi, baseB2);
    bf_stage<4, 16, true>(xr, xi, baseB2);
    bf_stage<8, 16, true>(xr, xi, baseB2);
    #pragma unroll
    for (int j = 0; j < 16; ++j) {
        int q = swz(baseB2 + (j << 4));
        pre[q] = xr[j]; pim[q] = xi[j];
    }
    __syncthreads();

    // ---- inverse group A: strides 256, 512; layout p = r + 64j ----
    #pragma unroll
    for (int j = 0; j < 16; ++j) {
        int q = swz(r + (j << 6));
        xr[j] = pre[q]; xi[j] = pim[q];
    }
    bf_stage<4, 64, true>(xr, xi, r);
    bf_stage<8, 64, true>(xr, xi, r);
    // only first 512 positions are emitted (j < 8)
    #pragma unroll
    for (int j = 0; j < 8; ++j) {
        int q = swz(r + (j << 6));
        pre[q] = xr[j]; pim[q] = xi[j];
    }
    __syncthreads();

    // ---- smem -> global: out_flat[s*8192 + bi] ; imag row is bi + 4096 ----
    float* __restrict__ ore = out + bc * 512 + a0;
    float* __restrict__ oim = out + (bc + 8) * 512 + a0;
    #pragma unroll
    for (int k = 0; k < 8; ++k) {
        int idx  = tid + NTHREADS * k;
        int row2 = idx & 7;
        int s    = idx >> 3;
        int qb   = row2 * PLANE;
        ore[s * 8192 + row2] = sre[qb + swz(s)];
        oim[s * 8192 + row2] = sim[qb + swz(s)];
    }
}

extern "C" void kernel_launch(void* const* d_in, const int* in_sizes, int n_in,
                              void* d_out, int out_size) {
    (void)in_sizes; (void)n_in; (void)out_size;
    const float* x    = (const float*)d_in[0];
    const float* filt = (const float*)d_in[3];   // fourier_filter_br (bit-reversed order)
    float* out = (float*)d_out;

    const size_t smem_bytes = (size_t)2 * ROWS * PLANE * sizeof(float);  // 69888
    cudaFuncSetAttribute(fbp_kernel, cudaFuncAttributeMaxDynamicSharedMemorySize,
                         (int)smem_bytes);
    fbp_kernel<<<512, NTHREADS, smem_bytes>>>(x, filt, out);
}

// round 2
// speedup vs baseline: 1.0689x; 1.0689x over previous
#include <cuda_runtime.h>

#define NFFT     1024
#define PLANE    1092            // 1024 + swizzle headroom; PLANE % 32 == 4
#define ROWS     8               // packed complex rows per CTA (= 16 real rows)
#define NTHREADS 512
#define PI_F     3.14159265358979323846f

__device__ __forceinline__ int swz(int p) { return p + (p >> 4); }

// One radix-2 stage on 16 register-resident complex elements.
// Pairs (j, j+H) for j&H==0; twiddle index = base_eff + D*(j&(H-1)), verified
// wrap-free (< S) for every call site, so angles form an exact arithmetic
// sequence: one __sincosf for k=0, then chained multiply by the constant
// ratio e^{∓i*pi/H}.
template<int H, int D, bool INV>
__device__ __forceinline__ void bf_stage(float* xr, float* xi, int base_eff) {
    const int S = D * H;
    const float coef = (INV ? PI_F : -PI_F) / (float)S;
    float ws, wc;
    __sincosf(coef * (float)base_eff, &ws, &wc);
    // ratio = e^{i*coef*D} = (cos(pi/H), ∓sin(pi/H))
    float dc, ds;
    if (H == 8)      { dc = 0.9238795325112867f; ds = 0.3826834323650898f; }
    else if (H == 4) { dc = 0.7071067811865476f; ds = 0.7071067811865476f; }
    else if (H == 2) { dc = 0.0f;                ds = 1.0f; }
    else             { dc = -1.0f;               ds = 0.0f; }
    if (!INV) ds = -ds;

    #pragma unroll
    for (int k = 0; k < H; ++k) {
        #pragma unroll
        for (int g = 0; g < 16 / (2 * H); ++g) {
            const int j  = g * 2 * H + k;
            const int j2 = j + H;
            if (!INV) {
                float tr = xr[j] - xr[j2];
                float ti = xi[j] - xi[j2];
                xr[j] += xr[j2];
                xi[j] += xi[j2];
                xr[j2] = tr * wc - ti * ws;
                xi[j2] = tr * ws + ti * wc;
            } else {
                float tr = xr[j2] * wc - xi[j2] * ws;
                float ti = xr[j2] * ws + xi[j2] * wc;
                xr[j2] = xr[j] - tr;
                xi[j2] = xi[j] - ti;
                xr[j]  += tr;
                xi[j]  += ti;
            }
        }
        float nc = wc * dc - ws * ds;   // advance twiddle
        ws = wc * ds + ws * dc;
        wc = nc;
    }
}

// One CTA: 8 packed complex rows (real rows bi and bi+4096, bi = bc*512 + a0+row).
// 64 threads per row, 16 complex elements per thread.
__global__ void __launch_bounds__(NTHREADS, 2)
fbp_kernel(const float* __restrict__ x, const float* __restrict__ filt,
           float* __restrict__ out)
{
    extern __shared__ float smem[];
    float* sre = smem;
    float* sim = smem + ROWS * PLANE;

    const int tid = threadIdx.x;
    const int bc  = blockIdx.x >> 6;         // 0..7
    const int a0  = (blockIdx.x & 63) << 3;  // 0..504 step 8

    const float* __restrict__ xre = x + bc * 262144 + a0;        // real-part rows
    const float* __restrict__ xim = x + (bc + 8) * 262144 + a0;  // imag-part rows

    // ---- global -> smem (coalesced 32B sectors); zeros handled in registers ----
    #pragma unroll
    for (int k = 0; k < 8; ++k) {
        int idx  = tid + NTHREADS * k;   // 0..4095
        int row  = idx & 7;
        int s    = idx >> 3;             // 0..511
        float vr = __ldg(xre + s * 512 + row);
        float vi = __ldg(xim + s * 512 + row);
        int qb = row * PLANE;
        sre[qb + swz(s)] = vr;
        sim[qb + swz(s)] = vi;
    }
    __syncthreads();

    const int row = tid >> 6;    // 0..7
    const int r   = tid & 63;    // 0..63
    float* __restrict__ pre = sre + row * PLANE;
    float* __restrict__ pim = sim + row * PLANE;

    float xr[16], xi[16];

    // ---- forward group A: layout p = r + 64j; p>=512 (j>=8) is the zero pad ----
    #pragma unroll
    for (int j = 0; j < 8; ++j) {
        int q = swz(r + (j << 6));
        xr[j] = pre[q]; xi[j] = pim[q];
    }
    #pragma unroll
    for (int j = 8; j < 16; ++j) { xr[j] = 0.0f; xi[j] = 0.0f; }
    bf_stage<8, 64, false>(xr, xi, r);
    bf_stage<4, 64, false>(xr, xi, r);
    bf_stage<2, 64, false>(xr, xi, r);
    bf_stage<1, 64, false>(xr, xi, r);
    #pragma unroll
    for (int j = 0; j < 16; ++j) {
        int q = swz(r + (j << 6));
        pre[q] = xr[j]; pim[q] = xi[j];
    }
    __syncthreads();

    // ---- forward group B: layout p = (r>>2)*64 + (r&3) + 4j; base_eff = r&3 ----
    const int baseB = ((r >> 2) << 6) + (r & 3);
    #pragma unroll
    for (int j = 0; j < 16; ++j) {
        int q = swz(baseB + (j << 2));
        xr[j] = pre[q]; xi[j] = pim[q];
    }
    bf_stage<8, 4, false>(xr, xi, r & 3);
    bf_stage<4, 4, false>(xr, xi, r & 3);
    bf_stage<2, 4, false>(xr, xi, r & 3);
    bf_stage<1, 4, false>(xr, xi, r & 3);
    #pragma unroll
    for (int j = 0; j < 16; ++j) {
        int q = swz(baseB + (j << 2));
        pre[q] = xr[j]; pim[q] = xi[j];
    }
    __syncthreads();

    // ---- forward group C + filter + inverse group C (no exchange at junction) ----
    // layout p = 16r + j (contiguous); base_eff = 0 for all C stages (compile-time twiddles)
    const int baseC = r << 4;
    #pragma unroll
    for (int j = 0; j < 16; ++j) {
        int q = swz(baseC + j);
        xr[j] = pre[q]; xi[j] = pim[q];
    }
    bf_stage<2, 1, false>(xr, xi, 0);
    bf_stage<1, 1, false>(xr, xi, 0);
    #pragma unroll
    for (int j = 0; j < 16; ++j) {   // filter in bit-reversed domain; fold 1/n scale
        float f = __ldg(filt + baseC + j) * (1.0f / 1024.0f);
        xr[j] *= f; xi[j] *= f;
    }
    bf_stage<1, 1, true>(xr, xi, 0);
    bf_stage<2, 1, true>(xr, xi, 0);
    bf_stage<4, 1, true>(xr, xi, 0);
    bf_stage<8, 1, true>(xr, xi, 0);
    #pragma unroll
    for (int j = 0; j < 16; ++j) {
        int q = swz(baseC + j);
        pre[q] = xr[j]; pim[q] = xi[j];
    }
    __syncthreads();

    // ---- inverse group B2: layout p = (r>>4)*256 + (r&15) + 16j; base_eff = r&15 ----
    const int baseB2 = ((r >> 4) << 8) + (r & 15);
    #pragma unroll
    for (int j = 0; j < 16; ++j) {
        int q = swz(baseB2 + (j << 4));
        xr[j] = pre[q]; xi[j] = pim[q];
    }
    bf_stage<1, 16, true>(xr, xi, r & 15);
    bf_stage<2, 16, true>(xr, xi, r & 15);
    bf_stage<4, 16, true>(xr, xi, r & 15);
    bf_stage<8, 16, true>(xr, xi, r & 15);
    #pragma unroll
    for (int j = 0; j < 16; ++j) {
        int q = swz(baseB2 + (j << 4));
        pre[q] = xr[j]; pim[q] = xi[j];
    }
    __syncthreads();

    // ---- inverse group A: strides 256, 512; layout p = r + 64j; base_eff = r ----
    #pragma unroll
    for (int j = 0; j < 16; ++j) {
        int q = swz(r + (j << 6));
        xr[j] = pre[q]; xi[j] = pim[q];
    }
    bf_stage<4, 64, true>(xr, xi, r);
    bf_stage<8, 64, true>(xr, xi, r);
    // only first 512 positions are emitted (j < 8)
    #pragma unroll
    for (int j = 0; j < 8; ++j) {
        int q = swz(r + (j << 6));
        pre[q] = xr[j]; pim[q] = xi[j];
    }
    __syncthreads();

    // ---- smem -> global: out_flat[s*8192 + bi] ; imag row is bi + 4096 ----
    float* __restrict__ ore = out + bc * 512 + a0;
    float* __restrict__ oim = out + (bc + 8) * 512 + a0;
    #pragma unroll
    for (int k = 0; k < 8; ++k) {
        int idx  = tid + NTHREADS * k;
        int row2 = idx & 7;
        int s    = idx >> 3;
        int qb   = row2 * PLANE;
        ore[s * 8192 + row2] = sre[qb + swz(s)];
        oim[s * 8192 + row2] = sim[qb + swz(s)];
    }
}

extern "C" void kernel_launch(void* const* d_in, const int* in_sizes, int n_in,
                              void* d_out, int out_size) {
    (void)in_sizes; (void)n_in; (void)out_size;
    const float* x    = (const float*)d_in[0];
    const float* filt = (const float*)d_in[3];   // fourier_filter_br (bit-reversed order)
    float* out = (float*)d_out;

    const size_t smem_bytes = (size_t)2 * ROWS * PLANE * sizeof(float);  // 69888
    cudaFuncSetAttribute(fbp_kernel, cudaFuncAttributeMaxDynamicSharedMemorySize,
                         (int)smem_bytes);
    fbp_kernel<<<512, NTHREADS, smem_bytes>>>(x, filt, out);
}

// round 3
// speedup vs baseline: 1.1156x; 1.0437x over previous
#include <cuda_runtime.h>

#define NFFT     1024
#define PLANE2   1090            // float2 pitch; >=1087 needed, 1090 % 16 == 2
#define ROWS     8               // packed complex rows per CTA (= 16 real rows)
#define NTHREADS 512
#define PI_F     3.14159265358979323846f

__device__ __forceinline__ int swz8(int p) { return p + (p >> 4); }

// One radix-2 stage on 16 register-resident complex elements.
// Pairs (j, j+H) for j&H==0; twiddle angle = coef*(base_eff + D*(j&(H-1))),
// verified wrap-free at all call sites. w_k = w0 * e^{∓i*pi*k/H} with constant
// c_k -> one __sincosf per stage, all k-twiddles independent (no serial chain).
template<int H, int D, bool INV>
__device__ __forceinline__ void bf_stage(float* xr, float* xi, int base_eff) {
    const int S = D * H;
    const float coef = (INV ? PI_F : -PI_F) / (float)S;
    float w0s, w0c;
    __sincosf(coef * (float)base_eff, &w0s, &w0c);

    // tables: cos/sin(pi*t/8), t = k*8/H
    constexpr float C8[8] = {1.0f, 0.9238795325112867f, 0.7071067811865476f,
                             0.3826834323650898f, 0.0f, -0.3826834323650898f,
                             -0.7071067811865476f, -0.9238795325112867f};
    constexpr float S8[8] = {0.0f, 0.3826834323650898f, 0.7071067811865476f,
                             0.9238795325112867f, 1.0f, 0.9238795325112867f,
                             0.7071067811865476f, 0.3826834323650898f};

    #pragma unroll
    for (int k = 0; k < H; ++k) {
        const int t = k * (8 / H);
        const float ckr = C8[t];
        const float cki = INV ? S8[t] : -S8[t];
        const float wc = w0c * ckr - w0s * cki;
        const float ws = w0s * ckr + w0c * cki;
        #pragma unroll
        for (int g = 0; g < 16 / (2 * H); ++g) {
            const int j  = g * 2 * H + k;
            const int j2 = j + H;
            if (!INV) {
                float tr = xr[j] - xr[j2];
                float ti = xi[j] - xi[j2];
                xr[j] += xr[j2];
                xi[j] += xi[j2];
                xr[j2] = tr * wc - ti * ws;
                xi[j2] = tr * ws + ti * wc;
            } else {
                float tr = xr[j2] * wc - xi[j2] * ws;
                float ti = xr[j2] * ws + xi[j2] * wc;
                xr[j2] = xr[j] - tr;
                xi[j2] = xi[j] - ti;
                xr[j]  += tr;
                xi[j]  += ti;
            }
        }
    }
}

// One CTA: 8 packed complex rows (real rows bi and bi+4096, bi = bc*512 + a0+row).
// 64 threads per row, 16 complex elements (float2) per thread. smem is float2.
__global__ void __launch_bounds__(NTHREADS, 2)
fbp_kernel(const float* __restrict__ x, const float* __restrict__ filt,
           float* __restrict__ out)
{
    extern __shared__ float2 sm[];

    const int tid = threadIdx.x;
    const int bc  = blockIdx.x >> 6;         // 0..7
    const int a0  = (blockIdx.x & 63) << 3;  // 0..504 step 8

    const float* __restrict__ xre = x + bc * 262144 + a0;        // real-part rows
    const float* __restrict__ xim = x + (bc + 8) * 262144 + a0;  // imag-part rows

    // ---- global -> smem (coalesced 32B sectors); zero pad handled in regs ----
    #pragma unroll
    for (int k = 0; k < 8; ++k) {
        int idx  = tid + NTHREADS * k;   // 0..4095
        int row  = idx & 7;
        int s    = idx >> 3;             // 0..511
        float vr = __ldg(xre + s * 512 + row);
        float vi = __ldg(xim + s * 512 + row);
        sm[row * PLANE2 + swz8(s)] = make_float2(vr, vi);
    }
    __syncthreads();

    const int row = tid >> 6;    // 0..7
    const int r   = tid & 63;    // 0..63
    float2* __restrict__ pp = sm + row * PLANE2;

    float xr[16], xi[16];

    // ---- forward group A: p = r + 64j; j>=8 is the zero pad ----
    #pragma unroll
    for (int j = 0; j < 8; ++j) {
        float2 v = pp[swz8(r + (j << 6))];
        xr[j] = v.x; xi[j] = v.y;
    }
    #pragma unroll
    for (int j = 8; j < 16; ++j) { xr[j] = 0.0f; xi[j] = 0.0f; }
    bf_stage<8, 64, false>(xr, xi, r);
    bf_stage<4, 64, false>(xr, xi, r);
    bf_stage<2, 64, false>(xr, xi, r);
    bf_stage<1, 64, false>(xr, xi, r);
    #pragma unroll
    for (int j = 0; j < 16; ++j)
        pp[swz8(r + (j << 6))] = make_float2(xr[j], xi[j]);
    __syncthreads();

    // ---- forward group B: p = (r>>2)*64 + (r&3) + 4j; base_eff = r&3 ----
    const int baseB = ((r >> 2) << 6) + (r & 3);
    #pragma unroll
    for (int j = 0; j < 16; ++j) {
        float2 v = pp[swz8(baseB + (j << 2))];
        xr[j] = v.x; xi[j] = v.y;
    }
    bf_stage<8, 4, false>(xr, xi, r & 3);
    bf_stage<4, 4, false>(xr, xi, r & 3);
    bf_stage<2, 4, false>(xr, xi, r & 3);
    bf_stage<1, 4, false>(xr, xi, r & 3);
    #pragma unroll
    for (int j = 0; j < 16; ++j)
        pp[swz8(baseB + (j << 2))] = make_float2(xr[j], xi[j]);
    __syncthreads();

    // ---- forward C + filter + inverse C (no exchange at junction) ----
    const int baseC = r << 4;    // p = 16r + j, contiguous; twiddles all constant
    #pragma unroll
    for (int j = 0; j < 16; ++j) {
        float2 v = pp[swz8(baseC + j)];
        xr[j] = v.x; xi[j] = v.y;
    }
    bf_stage<2, 1, false>(xr, xi, 0);
    bf_stage<1, 1, false>(xr, xi, 0);
    #pragma unroll
    for (int j = 0; j < 16; ++j) {   // filter in bit-reversed domain; fold 1/n
        float f = __ldg(filt + baseC + j) * (1.0f / 1024.0f);
        xr[j] *= f; xi[j] *= f;
    }
    bf_stage<1, 1, true>(xr, xi, 0);
    bf_stage<2, 1, true>(xr, xi, 0);
    bf_stage<4, 1, true>(xr, xi, 0);
    bf_stage<8, 1, true>(xr, xi, 0);
    #pragma unroll
    for (int j = 0; j < 16; ++j)
        pp[swz8(baseC + j)] = make_float2(xr[j], xi[j]);
    __syncthreads();

    // ---- inverse group B2: p = (r>>4)*256 + (r&15) + 16j; base_eff = r&15 ----
    const int baseB2 = ((r >> 4) << 8) + (r & 15);
    #pragma unroll
    for (int j = 0; j < 16; ++j) {
        float2 v = pp[swz8(baseB2 + (j << 4))];
        xr[j] = v.x; xi[j] = v.y;
    }
    bf_stage<1, 16, true>(xr, xi, r & 15);
    bf_stage<2, 16, true>(xr, xi, r & 15);
    bf_stage<4, 16, true>(xr, xi, r & 15);
    bf_stage<8, 16, true>(xr, xi, r & 15);
    #pragma unroll
    for (int j = 0; j < 16; ++j)
        pp[swz8(baseB2 + (j << 4))] = make_float2(xr[j], xi[j]);
    __syncthreads();

    // ---- inverse group A: strides 256, 512; p = r + 64j; base_eff = r ----
    #pragma unroll
    for (int j = 0; j < 16; ++j) {
        float2 v = pp[swz8(r + (j << 6))];
        xr[j] = v.x; xi[j] = v.y;
    }
    bf_stage<4, 64, true>(xr, xi, r);
    bf_stage<8, 64, true>(xr, xi, r);
    // only first 512 positions are emitted (j < 8)
    #pragma unroll
    for (int j = 0; j < 8; ++j)
        pp[swz8(r + (j << 6))] = make_float2(xr[j], xi[j]);
    __syncthreads();

    // ---- smem -> global: out[s*8192 + bi], imag row at bi + 4096 ----
    float* __restrict__ ore = out + bc * 512 + a0;
    float* __restrict__ oim = out + (bc + 8) * 512 + a0;
    #pragma unroll
    for (int k = 0; k < 8; ++k) {
        int idx  = tid + NTHREADS * k;
        int row2 = idx & 7;
        int s    = idx >> 3;
        float2 v = sm[row2 * PLANE2 + swz8(s)];
        ore[s * 8192 + row2] = v.x;
        oim[s * 8192 + row2] = v.y;
    }
}

extern "C" void kernel_launch(void* const* d_in, const int* in_sizes, int n_in,
                              void* d_out, int out_size) {
    (void)in_sizes; (void)n_in; (void)out_size;
    const float* x    = (const float*)d_in[0];
    const float* filt = (const float*)d_in[3];   // fourier_filter_br
    float* out = (float*)d_out;

    const size_t smem_bytes = (size_t)ROWS * PLANE2 * sizeof(float2);  // 69760
    cudaFuncSetAttribute(fbp_kernel, cudaFuncAttributeMaxDynamicSharedMemorySize,
                         (int)smem_bytes);
    fbp_kernel<<<512, NTHREADS, smem_bytes>>>(x, filt, out);
}

// round 4
// speedup vs baseline: 1.3228x; 1.1858x over previous
#include <cuda_runtime.h>

#define PLANE2   1090            // float2 pitch; 1090 % 16 == 2
#define ROWS     8               // packed complex rows per CTA (= 16 real rows)
#define NTHREADS 512
#define PI_F     3.14159265358979323846f

__device__ __forceinline__ int swz8(int p) { return p + (p >> 4); }

// One radix-2 stage on 16 register-resident complex elements.
// Pairs (j, j+H) for j&H==0; twiddle angle = coef*(base_eff + D*k), k=j&(H-1),
// wrap-free at all call sites. w_k = w0 * e^{∓i*pi*k/H}; constants from table.
// B0=true -> base_eff==0 -> w0=(1,0), no sincos, fully constant twiddles.
template<int H, int D, bool INV, bool B0>
__device__ __forceinline__ void bf_stage(float* xr, float* xi, int base_eff) {
    const int S = D * H;
    const float coef = (INV ? PI_F : -PI_F) / (float)S;
    float w0s, w0c;
    if (B0) { w0c = 1.0f; w0s = 0.0f; }
    else    { __sincosf(coef * (float)base_eff, &w0s, &w0c); }

    constexpr float C8[8] = {1.0f, 0.9238795325112867f, 0.7071067811865476f,
                             0.3826834323650898f, 0.0f, -0.3826834323650898f,
                             -0.7071067811865476f, -0.9238795325112867f};
    constexpr float S8[8] = {0.0f, 0.3826834323650898f, 0.7071067811865476f,
                             0.9238795325112867f, 1.0f, 0.9238795325112867f,
                             0.7071067811865476f, 0.3826834323650898f};

    #pragma unroll
    for (int k = 0; k < H; ++k) {
        const int t = k * (8 / H);
        const float ckr = C8[t];
        const float cki = INV ? S8[t] : -S8[t];
        const float wc = B0 ? ckr : (w0c * ckr - w0s * cki);
        const float ws = B0 ? cki : (w0s * ckr + w0c * cki);
        #pragma unroll
        for (int g = 0; g < 16 / (2 * H); ++g) {
            const int j  = g * 2 * H + k;
            const int j2 = j + H;
            if (!INV) {
                float tr = xr[j] - xr[j2];
                float ti = xi[j] - xi[j2];
                xr[j] += xr[j2];
                xi[j] += xi[j2];
                xr[j2] = tr * wc - ti * ws;
                xi[j2] = tr * ws + ti * wc;
            } else {
                float tr = xr[j2] * wc - xi[j2] * ws;
                float ti = xr[j2] * ws + xi[j2] * wc;
                xr[j2] = xr[j] - tr;
                xi[j2] = xi[j] - ti;
                xr[j]  += tr;
                xi[j]  += ti;
            }
        }
    }
}

// One CTA: 8 packed complex rows (real rows bi and bi+4096, bi = bc*512 + a0+row).
// 64 threads per row, 16 complex elements per thread. Stage split 4+2+4 so every
// smem access pattern is affine in the unrolled index (const LDS/STS offsets).
__global__ void __launch_bounds__(NTHREADS, 2)
fbp_kernel(const float* __restrict__ x, const float* __restrict__ filt,
           float* __restrict__ out)
{
    extern __shared__ float2 sm[];

    const int tid = threadIdx.x;
    const int bc  = blockIdx.x >> 6;         // 0..7
    const int a0  = (blockIdx.x & 63) << 3;  // 0..504 step 8

    const float* __restrict__ xre = x + bc * 262144 + a0;        // real rows
    const float* __restrict__ xim = x + (bc + 8) * 262144 + a0;  // imag rows

    // ---- global -> smem: LDG.128 over 4 consecutive a (rows), per s ----
    #pragma unroll
    for (int k = 0; k < 2; ++k) {
        int v  = tid + NTHREADS * k;     // 0..1023
        int rq = v & 1;                  // 4-row group
        int s  = v >> 1;                 // 0..511
        float4 re4 = *reinterpret_cast<const float4*>(xre + s * 512 + 4 * rq);
        float4 im4 = *reinterpret_cast<const float4*>(xim + s * 512 + 4 * rq);
        int q = swz8(s);
        sm[(4 * rq + 0) * PLANE2 + q] = make_float2(re4.x, im4.x);
        sm[(4 * rq + 1) * PLANE2 + q] = make_float2(re4.y, im4.y);
        sm[(4 * rq + 2) * PLANE2 + q] = make_float2(re4.z, im4.z);
        sm[(4 * rq + 3) * PLANE2 + q] = make_float2(re4.w, im4.w);
    }
    __syncthreads();

    const int row = tid >> 6;    // 0..7
    const int r   = tid & 63;    // 0..63
    const int planeBase = row * PLANE2;
    const int bA = planeBase + r + (r >> 4);                    // stride 68 in j
    const int bM = planeBase + 272 * (r >> 4) + (r & 15);       // stride 17 in j
    const int bC = planeBase + 17 * r;                          // stride 1 in j

    float xr[16], xi[16];

    // ---- forward A: p = r + 64j (strides 512,256,128,64); j>=8 is zero pad ----
    #pragma unroll
    for (int j = 0; j < 8; ++j) {
        float2 v = sm[bA + 68 * j];
        xr[j] = v.x; xi[j] = v.y;
    }
    #pragma unroll
    for (int j = 8; j < 16; ++j) { xr[j] = 0.0f; xi[j] = 0.0f; }
    bf_stage<8, 64, false, false>(xr, xi, r);
    bf_stage<4, 64, false, false>(xr, xi, r);
    bf_stage<2, 64, false, false>(xr, xi, r);
    bf_stage<1, 64, false, false>(xr, xi, r);
    #pragma unroll
    for (int j = 0; j < 16; ++j) sm[bA + 68 * j] = make_float2(xr[j], xi[j]);
    __syncthreads();

    // ---- forward M: p = 256w + m + 16j (strides 32,16); base_eff = m ----
    #pragma unroll
    for (int j = 0; j < 16; ++j) {
        float2 v = sm[bM + 17 * j];
        xr[j] = v.x; xi[j] = v.y;
    }
    bf_stage<2, 16, false, false>(xr, xi, r & 15);
    bf_stage<1, 16, false, false>(xr, xi, r & 15);
    #pragma unroll
    for (int j = 0; j < 16; ++j) sm[bM + 17 * j] = make_float2(xr[j], xi[j]);
    __syncthreads();

    // ---- forward C' (strides 8,4,2,1) + filter + inverse C' (1,2,4,8) ----
    // p = 16r + j; base_eff = 0 -> all twiddles compile-time constants.
    #pragma unroll
    for (int j = 0; j < 16; ++j) {
        float2 v = sm[bC + j];
        xr[j] = v.x; xi[j] = v.y;
    }
    bf_stage<8, 1, false, true>(xr, xi, 0);
    bf_stage<4, 1, false, true>(xr, xi, 0);
    bf_stage<2, 1, false, true>(xr, xi, 0);
    bf_stage<1, 1, false, true>(xr, xi, 0);
    #pragma unroll
    for (int j = 0; j < 16; ++j) {   // filter in bit-reversed domain; fold 1/n
        float f = __ldg(filt + (r << 4) + j) * (1.0f / 1024.0f);
        xr[j] *= f; xi[j] *= f;
    }
    bf_stage<1, 1, true, true>(xr, xi, 0);
    bf_stage<2, 1, true, true>(xr, xi, 0);
    bf_stage<4, 1, true, true>(xr, xi, 0);
    bf_stage<8, 1, true, true>(xr, xi, 0);
    #pragma unroll
    for (int j = 0; j < 16; ++j) sm[bC + j] = make_float2(xr[j], xi[j]);
    __syncthreads();

    // ---- inverse M2: strides 16,32; base_eff = m ----
    #pragma unroll
    for (int j = 0; j < 16; ++j) {
        float2 v = sm[bM + 17 * j];
        xr[j] = v.x; xi[j] = v.y;
    }
    bf_stage<1, 16, true, false>(xr, xi, r & 15);
    bf_stage<2, 16, true, false>(xr, xi, r & 15);
    #pragma unroll
    for (int j = 0; j < 16; ++j) sm[bM + 17 * j] = make_float2(xr[j], xi[j]);
    __syncthreads();

    // ---- inverse A2: strides 64,128,256,512; base_eff = r ----
    #pragma unroll
    for (int j = 0; j < 16; ++j) {
        float2 v = sm[bA + 68 * j];
        xr[j] = v.x; xi[j] = v.y;
    }
    bf_stage<1, 64, true, false>(xr, xi, r);
    bf_stage<2, 64, true, false>(xr, xi, r);
    bf_stage<4, 64, true, false>(xr, xi, r);
    bf_stage<8, 64, true, false>(xr, xi, r);
    // only first 512 positions are emitted (j < 8)
    #pragma unroll
    for (int j = 0; j < 8; ++j) sm[bA + 68 * j] = make_float2(xr[j], xi[j]);
    __syncthreads();

    // ---- smem -> global: STG.128 over 4 consecutive bi, per s ----
    float* __restrict__ ore = out + bc * 512 + a0;
    float* __restrict__ oim = out + (bc + 8) * 512 + a0;
    #pragma unroll
    for (int k = 0; k < 2; ++k) {
        int v  = tid + NTHREADS * k;
        int rq = v & 1;
        int s  = v >> 1;
        int q = swz8(s);
        float2 v0 = sm[(4 * rq + 0) * PLANE2 + q];
        float2 v1 = sm[(4 * rq + 1) * PLANE2 + q];
        float2 v2 = sm[(4 * rq + 2) * PLANE2 + q];
        float2 v3 = sm[(4 * rq + 3) * PLANE2 + q];
        *reinterpret_cast<float4*>(ore + s * 8192 + 4 * rq) =
            make_float4(v0.x, v1.x, v2.x, v3.x);
        *reinterpret_cast<float4*>(oim + s * 8192 + 4 * rq) =
            make_float4(v0.y, v1.y, v2.y, v3.y);
    }
}

extern "C" void kernel_launch(void* const* d_in, const int* in_sizes, int n_in,
                              void* d_out, int out_size) {
    (void)in_sizes; (void)n_in; (void)out_size;
    const float* x    = (const float*)d_in[0];
    const float* filt = (const float*)d_in[3];   // fourier_filter_br
    float* out = (float*)d_out;

    const size_t smem_bytes = (size_t)ROWS * PLANE2 * sizeof(float2);  // 69760
    cudaFuncSetAttribute(fbp_kernel, cudaFuncAttributeMaxDynamicSharedMemorySize,
                         (int)smem_bytes);
    fbp_kernel<<<512, NTHREADS, smem_bytes>>>(x, filt, out);
}

// round 5
// speedup vs baseline: 1.4163x; 1.0707x over previous
#include <cuda_runtime.h>

#define PLANE2   1090            // float2 pitch; 1090 % 16 == 2
#define ROWS     8
#define NTHREADS 512
#define PI_F     3.14159265358979323846f

// One radix-2 stage on 16 register-resident complex elements.
// Pairs (j, j+H) for j&H==0; twiddle angle = coef*(base_eff + D*k), k=j&(H-1),
// wrap-free at all call sites. w_k = w0 * e^{∓i*pi*k/H}; constants from table.
template<int H, int D, bool INV, bool B0>
__device__ __forceinline__ void bf_stage(float* xr, float* xi, int base_eff) {
    const int S = D * H;
    const float coef = (INV ? PI_F : -PI_F) / (float)S;
    float w0s, w0c;
    if (B0) { w0c = 1.0f; w0s = 0.0f; }
    else    { __sincosf(coef * (float)base_eff, &w0s, &w0c); }

    constexpr float C8[8] = {1.0f, 0.9238795325112867f, 0.7071067811865476f,
                             0.3826834323650898f, 0.0f, -0.3826834323650898f,
                             -0.7071067811865476f, -0.9238795325112867f};
    constexpr float S8[8] = {0.0f, 0.3826834323650898f, 0.7071067811865476f,
                             0.9238795325112867f, 1.0f, 0.9238795325112867f,
                             0.7071067811865476f, 0.3826834323650898f};

    #pragma unroll
    for (int k = 0; k < H; ++k) {
        const int t = k * (8 / H);
        const float ckr = C8[t];
        const float cki = INV ? S8[t] : -S8[t];
        const float wc = B0 ? ckr : (w0c * ckr - w0s * cki);
        const float ws = B0 ? cki : (w0s * ckr + w0c * cki);
        #pragma unroll
        for (int g = 0; g < 16 / (2 * H); ++g) {
            const int j  = g * 2 * H + k;
            const int j2 = j + H;
            if (!INV) {
                float tr = xr[j] - xr[j2];
                float ti = xi[j] - xi[j2];
                xr[j] += xr[j2];
                xi[j] += xi[j2];
                xr[j2] = tr * wc - ti * ws;
                xi[j2] = tr * ws + ti * wc;
            } else {
                float tr = xr[j2] * wc - xi[j2] * ws;
                float ti = xr[j2] * ws + xi[j2] * wc;
                xr[j2] = xr[j] - tr;
                xi[j2] = xi[j] - ti;
                xr[j]  += tr;
                xi[j]  += ti;
            }
        }
    }
}

__device__ __forceinline__ void row_bar(int id) {
    asm volatile("bar.sync %0, 64;" :: "r"(id));
}

// One CTA: 8 packed complex rows (real rows bi and bi+4096, bi = bc*512 + a0+row).
// Group A / A2 run fused with global load/store (mapping row=tid&7, r=tid>>3,
// warp LDG/STG = 4 fully-used 32B sectors). Groups M, C, M2 use row=tid>>6 and
// row-scoped named barriers. Canonical smem layout addr:
//   A: row*PLANE2 + r + (r>>4) + 68j   (p = r + 64j)
//   M: row*PLANE2 + 272w + m + 17j     (p = 256w + m + 16j)
//   C: row*PLANE2 + 17r + j            (p = 16r + j)
__global__ void __launch_bounds__(NTHREADS, 2)
fbp_kernel(const float* __restrict__ x, const float* __restrict__ filt,
           float* __restrict__ out)
{
    extern __shared__ float2 sm[];

    const int tid = threadIdx.x;
    const int bc  = blockIdx.x >> 6;         // 0..7
    const int a0  = (blockIdx.x & 63) << 3;  // 0..504 step 8

    float xr[16], xi[16];

    // ================= phase A: direct global load + 4 fwd stages =================
    {
        const int rowL = tid & 7;        // a-offset
        const int rL   = tid >> 3;       // 0..63
        const float* __restrict__ xre = x + bc * 262144 + a0 + rowL;
        const float* __restrict__ xim = x + (bc + 8) * 262144 + a0 + rowL;

        #pragma unroll
        for (int j = 0; j < 8; ++j) {    // p = rL + 64j < 512
            xr[j] = __ldg(xre + (rL + 64 * j) * 512);
            xi[j] = __ldg(xim + (rL + 64 * j) * 512);
        }
        #pragma unroll
        for (int j = 8; j < 16; ++j) { xr[j] = 0.0f; xi[j] = 0.0f; }

        bf_stage<8, 64, false, false>(xr, xi, rL);
        bf_stage<4, 64, false, false>(xr, xi, rL);
        bf_stage<2, 64, false, false>(xr, xi, rL);
        bf_stage<1, 64, false, false>(xr, xi, rL);

        const int bAL = rowL * PLANE2 + rL + (rL >> 4);
        #pragma unroll
        for (int j = 0; j < 16; ++j)
            sm[bAL + 68 * j] = make_float2(xr[j], xi[j]);
    }
    __syncthreads();

    const int row = tid >> 6;    // 0..7
    const int r   = tid & 63;    // 0..63
    const int planeBase = row * PLANE2;
    const int bM = planeBase + 272 * (r >> 4) + (r & 15);   // stride 17 in j
    const int bC = planeBase + 17 * r;                      // stride 1 in j

    // ================= phase M: strides 32,16 =================
    #pragma unroll
    for (int j = 0; j < 16; ++j) {
        float2 v = sm[bM + 17 * j];
        xr[j] = v.x; xi[j] = v.y;
    }
    bf_stage<2, 16, false, false>(xr, xi, r & 15);
    bf_stage<1, 16, false, false>(xr, xi, r & 15);
    #pragma unroll
    for (int j = 0; j < 16; ++j) sm[bM + 17 * j] = make_float2(xr[j], xi[j]);
    row_bar(row + 1);

    // ====== phase C: fwd strides 8..1, filter, inverse strides 1..8 ======
    #pragma unroll
    for (int j = 0; j < 16; ++j) {
        float2 v = sm[bC + j];
        xr[j] = v.x; xi[j] = v.y;
    }
    bf_stage<8, 1, false, true>(xr, xi, 0);
    bf_stage<4, 1, false, true>(xr, xi, 0);
    bf_stage<2, 1, false, true>(xr, xi, 0);
    bf_stage<1, 1, false, true>(xr, xi, 0);
    #pragma unroll
    for (int j = 0; j < 16; ++j) {   // bit-reversed-domain filter; fold 1/n
        float f = __ldg(filt + (r << 4) + j) * (1.0f / 1024.0f);
        xr[j] *= f; xi[j] *= f;
    }
    bf_stage<1, 1, true, true>(xr, xi, 0);
    bf_stage<2, 1, true, true>(xr, xi, 0);
    bf_stage<4, 1, true, true>(xr, xi, 0);
    bf_stage<8, 1, true, true>(xr, xi, 0);
    #pragma unroll
    for (int j = 0; j < 16; ++j) sm[bC + j] = make_float2(xr[j], xi[j]);
    row_bar(row + 1);

    // ================= phase M2: strides 16,32 =================
    #pragma unroll
    for (int j = 0; j < 16; ++j) {
        float2 v = sm[bM + 17 * j];
        xr[j] = v.x; xi[j] = v.y;
    }
    bf_stage<1, 16, true, false>(xr, xi, r & 15);
    bf_stage<2, 16, true, false>(xr, xi, r & 15);
    #pragma unroll
    for (int j = 0; j < 16; ++j) sm[bM + 17 * j] = make_float2(xr[j], xi[j]);
    __syncthreads();

    // ======== phase A2: strides 64..512 + direct global store ========
    {
        const int rowL = tid & 7;
        const int rL   = tid >> 3;
        const int bAL = rowL * PLANE2 + rL + (rL >> 4);
        #pragma unroll
        for (int j = 0; j < 16; ++j) {
            float2 v = sm[bAL + 68 * j];
            xr[j] = v.x; xi[j] = v.y;
        }
        bf_stage<1, 64, true, false>(xr, xi, rL);
        bf_stage<2, 64, true, false>(xr, xi, rL);
        bf_stage<4, 64, true, false>(xr, xi, rL);
        bf_stage<8, 64, true, false>(xr, xi, rL);

        // emit p = rL + 64j for j<8 (p < 512): out[p*8192 + bi], imag at +4096
        float* __restrict__ ore = out + bc * 512 + a0 + rowL;
        float* __restrict__ oim = out + (bc + 8) * 512 + a0 + rowL;
        #pragma unroll
        for (int j = 0; j < 8; ++j) {
            int p = rL + 64 * j;
            ore[p * 8192] = xr[j];
            oim[p * 8192] = xi[j];
        }
    }
}

extern "C" void kernel_launch(void* const* d_in, const int* in_sizes, int n_in,
                              void* d_out, int out_size) {
    (void)in_sizes; (void)n_in; (void)out_size;
    const float* x    = (const float*)d_in[0];
    const float* filt = (const float*)d_in[3];   // fourier_filter_br
    float* out = (float*)d_out;

    const size_t smem_bytes = (size_t)ROWS * PLANE2 * sizeof(float2);  // 69760
    cudaFuncSetAttribute(fbp_kernel, cudaFuncAttributeMaxDynamicSharedMemorySize,
                         (int)smem_bytes);
    fbp_kernel<<<512, NTHREADS, smem_bytes>>>(x, filt, out);
}

// round 6
// speedup vs baseline: 1.6922x; 1.1948x over previous
#include <cuda_runtime.h>

#define PLANEW   1058            // float2 words per plane; 1058 % 16 == 2
#define NTHREADS 256
#define PI_F     3.14159265358979323846f

// One radix-2 stage on 32 register-resident complex elements.
// Pairs (j, j+H), j&H==0; position p = base + D*j; twiddle idx = base_eff + D*k,
// k = j&(H-1), wrap-free at all call sites. w_k = w0 * e^{∓i*pi*k/H}.
// B0=true -> base_eff==0 -> fully constant twiddles (no sincos).
template<int H, int D, bool INV, bool B0>
__device__ __forceinline__ void bf32(float* xr, float* xi, int base_eff) {
    const int S = D * H;
    const float coef = (INV ? PI_F : -PI_F) / (float)S;
    float w0s, w0c;
    if (B0) { w0c = 1.0f; w0s = 0.0f; }
    else    { __sincosf(coef * (float)base_eff, &w0s, &w0c); }

    // cos/sin(pi*t/16), t = k*16/H
    constexpr float C16[16] = {
        1.0f, 0.980785280403230449f, 0.923879532511286756f, 0.831469612302545237f,
        0.707106781186547524f, 0.555570233019602225f, 0.382683432365089772f,
        0.195090322016128268f, 0.0f, -0.195090322016128268f, -0.382683432365089772f,
        -0.555570233019602225f, -0.707106781186547524f, -0.831469612302545237f,
        -0.923879532511286756f, -0.980785280403230449f};
    constexpr float S16[16] = {
        0.0f, 0.195090322016128268f, 0.382683432365089772f, 0.555570233019602225f,
        0.707106781186547524f, 0.831469612302545237f, 0.923879532511286756f,
        0.980785280403230449f, 1.0f, 0.980785280403230449f, 0.923879532511286756f,
        0.831469612302545237f, 0.707106781186547524f, 0.555570233019602225f,
        0.382683432365089772f, 0.195090322016128268f};

    #pragma unroll
    for (int k = 0; k < H; ++k) {
        const int t = k * (16 / H);
        const float ckr = C16[t];
        const float cki = INV ? S16[t] : -S16[t];
        const float wc = B0 ? ckr : (w0c * ckr - w0s * cki);
        const float ws = B0 ? cki : (w0s * ckr + w0c * cki);
        #pragma unroll
        for (int g = 0; g < 32 / (2 * H); ++g) {
            const int j  = g * 2 * H + k;
            const int j2 = j + H;
            if (!INV) {
                float tr = xr[j] - xr[j2];
                float ti = xi[j] - xi[j2];
                xr[j] += xr[j2];
                xi[j] += xi[j2];
                xr[j2] = tr * wc - ti * ws;
                xi[j2] = tr * ws + ti * wc;
            } else {
                float tr = xr[j2] * wc - xi[j2] * ws;
                float ti = xr[j2] * ws + xi[j2] * wc;
                xr[j2] = xr[j] - tr;
                xi[j2] = xi[j] - ti;
                xr[j]  += tr;
                xi[j]  += ti;
            }
        }
    }
}

// One CTA: 8 packed complex rows (real rows bi and bi+4096, bi = bc*512 + a0+w).
// Warp w owns row w entirely: 32 threads x 32 complex elements.
// Plane layout: word(p) = 33*(p>>5) + (p&31), plane stride PLANEW.
//   A access: p = r + 32j -> addr = plane + r + 33j      (affine, CF)
//   C access: p = 32r + j -> addr = plane + 33r + j      (affine, CF)
__global__ void __launch_bounds__(NTHREADS, 2)
fbp_kernel(const float* __restrict__ x, const float* __restrict__ filt,
           float* __restrict__ out)
{
    extern __shared__ float2 sm[];

    const int tid = threadIdx.x;
    const int bc  = blockIdx.x >> 6;         // 0..7
    const int a0  = (blockIdx.x & 63) << 3;  // 0..504 step 8

    const float* __restrict__ xre = x + bc * 262144 + a0;
    const float* __restrict__ xim = x + (bc + 8) * 262144 + a0;

    // ---- distribute: LDG.128 over 4 consecutive a, scatter to planes ----
    #pragma unroll
    for (int k = 0; k < 4; ++k) {
        int idx = tid + NTHREADS * k;    // 0..1023
        int rq  = idx & 1;
        int s   = idx >> 1;              // 0..511
        float4 re4 = *reinterpret_cast<const float4*>(xre + s * 512 + 4 * rq);
        float4 im4 = *reinterpret_cast<const float4*>(xim + s * 512 + 4 * rq);
        int wd = 33 * (s >> 5) + (s & 31);
        sm[(4 * rq + 0) * PLANEW + wd] = make_float2(re4.x, im4.x);
        sm[(4 * rq + 1) * PLANEW + wd] = make_float2(re4.y, im4.y);
        sm[(4 * rq + 2) * PLANEW + wd] = make_float2(re4.z, im4.z);
        sm[(4 * rq + 3) * PLANEW + wd] = make_float2(re4.w, im4.w);
    }
    __syncthreads();

    const int w = tid >> 5;          // warp = plane/row
    const int r = tid & 31;
    const int plane = w * PLANEW;
    const int bA = plane + r;        // + 33j
    const int bC = plane + 33 * r;   // + j

    float xr[32], xi[32];

    // ======== phase A: p = r + 32j, strides 512,256,128,64,32 ========
    #pragma unroll
    for (int j = 0; j < 16; ++j) {   // p = r + 32j < 512
        float2 v = sm[bA + 33 * j];
        xr[j] = v.x; xi[j] = v.y;
    }
    #pragma unroll
    for (int j = 16; j < 32; ++j) { xr[j] = 0.0f; xi[j] = 0.0f; }
    bf32<16, 32, false, false>(xr, xi, r);
    bf32< 8, 32, false, false>(xr, xi, r);
    bf32< 4, 32, false, false>(xr, xi, r);
    bf32< 2, 32, false, false>(xr, xi, r);
    bf32< 1, 32, false, false>(xr, xi, r);
    #pragma unroll
    for (int j = 0; j < 32; ++j) sm[bA + 33 * j] = make_float2(xr[j], xi[j]);
    __syncwarp();

    // ======== phase C: p = 32r + j, fwd 16..1, filter, inv 1..16 ========
    #pragma unroll
    for (int j = 0; j < 32; ++j) {
        float2 v = sm[bC + j];
        xr[j] = v.x; xi[j] = v.y;
    }
    bf32<16, 1, false, true>(xr, xi, 0);
    bf32< 8, 1, false, true>(xr, xi, 0);
    bf32< 4, 1, false, true>(xr, xi, 0);
    bf32< 2, 1, false, true>(xr, xi, 0);
    bf32< 1, 1, false, true>(xr, xi, 0);
    {
        const float4* __restrict__ f4 =
            reinterpret_cast<const float4*>(filt + 32 * r);
        #pragma unroll
        for (int i = 0; i < 8; ++i) {   // bit-reversed-domain filter; fold 1/n
            float4 f = __ldg(f4 + i);
            xr[4*i+0] *= f.x * (1.0f/1024.0f); xi[4*i+0] *= f.x * (1.0f/1024.0f);
            xr[4*i+1] *= f.y * (1.0f/1024.0f); xi[4*i+1] *= f.y * (1.0f/1024.0f);
            xr[4*i+2] *= f.z * (1.0f/1024.0f); xi[4*i+2] *= f.z * (1.0f/1024.0f);
            xr[4*i+3] *= f.w * (1.0f/1024.0f); xi[4*i+3] *= f.w * (1.0f/1024.0f);
        }
    }
    bf32< 1, 1, true, true>(xr, xi, 0);
    bf32< 2, 1, true, true>(xr, xi, 0);
    bf32< 4, 1, true, true>(xr, xi, 0);
    bf32< 8, 1, true, true>(xr, xi, 0);
    bf32<16, 1, true, true>(xr, xi, 0);
    #pragma unroll
    for (int j = 0; j < 32; ++j) sm[bC + j] = make_float2(xr[j], xi[j]);
    __syncwarp();

    // ======== phase A2: p = r + 32j, strides 32,64,128,256,512 ========
    #pragma unroll
    for (int j = 0; j < 32; ++j) {
        float2 v = sm[bA + 33 * j];
        xr[j] = v.x; xi[j] = v.y;
    }
    bf32< 1, 32, true, false>(xr, xi, r);
    bf32< 2, 32, true, false>(xr, xi, r);
    bf32< 4, 32, true, false>(xr, xi, r);
    bf32< 8, 32, true, false>(xr, xi, r);
    bf32<16, 32, true, false>(xr, xi, r);
    #pragma unroll
    for (int j = 0; j < 16; ++j)     // only p < 512 emitted
        sm[bA + 33 * j] = make_float2(xr[j], xi[j]);
    __syncthreads();

    // ---- gather: planes -> STG.128 over 4 consecutive bi per s ----
    float* __restrict__ ore = out + bc * 512 + a0;
    float* __restrict__ oim = out + (bc + 8) * 512 + a0;
    #pragma unroll
    for (int k = 0; k < 4; ++k) {
        int idx = tid + NTHREADS * k;
        int rq  = idx & 1;
        int s   = idx >> 1;
        int wd = 33 * (s >> 5) + (s & 31);
        float2 v0 = sm[(4 * rq + 0) * PLANEW + wd];
        float2 v1 = sm[(4 * rq + 1) * PLANEW + wd];
        float2 v2 = sm[(4 * rq + 2) * PLANEW + wd];
        float2 v3 = sm[(4 * rq + 3) * PLANEW + wd];
        *reinterpret_cast<float4*>(ore + s * 8192 + 4 * rq) =
            make_float4(v0.x, v1.x, v2.x, v3.x);
        *reinterpret_cast<float4*>(oim + s * 8192 + 4 * rq) =
            make_float4(v0.y, v1.y, v2.y, v3.y);
    }
}

extern "C" void kernel_launch(void* const* d_in, const int* in_sizes, int n_in,
                              void* d_out, int out_size) {
    (void)in_sizes; (void)n_in; (void)out_size;
    const float* x    = (const float*)d_in[0];
    const float* filt = (const float*)d_in[3];   // fourier_filter_br
    float* out = (float*)d_out;

    const size_t smem_bytes = (size_t)8 * PLANEW * sizeof(float2);  // 67712
    cudaFuncSetAttribute(fbp_kernel, cudaFuncAttributeMaxDynamicSharedMemorySize,
                         (int)smem_bytes);
    fbp_kernel<<<512, NTHREADS, smem_bytes>>>(x, filt, out);
}